// round 1
// baseline (speedup 1.0000x reference)
#include <cuda_runtime.h>
#include <cstdint>

// Problem constants
#define BATCH 2
#define SEQ   2048
#define HID   1024
#define NHEAD 16
#define HDIM  64
#define ROWS  (BATCH * SEQ)      // 4096

// ---------------- scratch (static device allocations; no cudaMalloc) --------
__device__ float g_Q[ROWS * HID];
__device__ float g_K[ROWS * HID];
__device__ float g_V[ROWS * HID];
__device__ float g_ATT[ROWS * HID];
__device__ float g_S[BATCH * NHEAD * HDIM * HDIM];   // 131072 floats

// ---------------- SGEMM: C[M,N] = A[M,Kg] * B[N,Kg]^T  (row-major) ----------
// Tile 128x128x16, 256 threads, 8x8 per-thread micro-tile.
#define BM 128
#define BN 128
#define BKK 16

__global__ __launch_bounds__(256, 2)
void sgemm_abT(const float* __restrict__ A, const float* __restrict__ B,
               float* __restrict__ C, int Mg, int Ng, int Kg) {
    __shared__ float As[BKK][BM];
    __shared__ float Bs[BKK][BN];

    const int tid = threadIdx.x;
    const int tx = tid & 15;          // 0..15 -> N micro
    const int ty = tid >> 4;          // 0..15 -> M micro
    const int bm = blockIdx.y * BM;
    const int bn = blockIdx.x * BN;

    const float* Ab = A + (size_t)bm * Kg;
    const float* Bb = B + (size_t)bn * Kg;

    float acc[8][8];
#pragma unroll
    for (int i = 0; i < 8; ++i)
#pragma unroll
        for (int j = 0; j < 8; ++j) acc[i][j] = 0.0f;

    for (int k0 = 0; k0 < Kg; k0 += BKK) {
        // Load A tile (128x16) and B tile (128x16), transposed into smem.
        // 512 float4 each; 2 per thread.
#pragma unroll
        for (int it = 0; it < 2; ++it) {
            int idx = tid + it * 256;
            int row = idx >> 2;
            int kq  = (idx & 3) * 4;
            float4 va = *(const float4*)(Ab + (size_t)row * Kg + k0 + kq);
            As[kq + 0][row] = va.x;
            As[kq + 1][row] = va.y;
            As[kq + 2][row] = va.z;
            As[kq + 3][row] = va.w;
            float4 vb = *(const float4*)(Bb + (size_t)row * Kg + k0 + kq);
            Bs[kq + 0][row] = vb.x;
            Bs[kq + 1][row] = vb.y;
            Bs[kq + 2][row] = vb.z;
            Bs[kq + 3][row] = vb.w;
        }
        __syncthreads();

#pragma unroll
        for (int kk = 0; kk < BKK; ++kk) {
            float a[8], b[8];
            float4 a0 = *(const float4*)&As[kk][ty * 8];
            float4 a1 = *(const float4*)&As[kk][ty * 8 + 4];
            float4 b0 = *(const float4*)&Bs[kk][tx * 8];
            float4 b1 = *(const float4*)&Bs[kk][tx * 8 + 4];
            a[0]=a0.x; a[1]=a0.y; a[2]=a0.z; a[3]=a0.w;
            a[4]=a1.x; a[5]=a1.y; a[6]=a1.z; a[7]=a1.w;
            b[0]=b0.x; b[1]=b0.y; b[2]=b0.z; b[3]=b0.w;
            b[4]=b1.x; b[5]=b1.y; b[6]=b1.z; b[7]=b1.w;
#pragma unroll
            for (int i = 0; i < 8; ++i)
#pragma unroll
                for (int j = 0; j < 8; ++j)
                    acc[i][j] = fmaf(a[i], b[j], acc[i][j]);
        }
        __syncthreads();
    }

    // Write back: rows bm+ty*8+i, cols bn+tx*8+(0..7)
#pragma unroll
    for (int i = 0; i < 8; ++i) {
        float* Crow = C + (size_t)(bm + ty * 8 + i) * Ng + bn + tx * 8;
        float4 c0 = make_float4(acc[i][0], acc[i][1], acc[i][2], acc[i][3]);
        float4 c1 = make_float4(acc[i][4], acc[i][5], acc[i][6], acc[i][7]);
        *(float4*)(Crow)     = c0;
        *(float4*)(Crow + 4) = c1;
    }
}

// ---------------- zero S ----------------------------------------------------
__global__ void zero_kernel(float* __restrict__ p, int n) {
    int i = blockIdx.x * blockDim.x + threadIdx.x;
    if (i < n) p[i] = 0.0f;
}

// ---------------- S[b,h] = K_h^T @ V_h  (64x64, reduce over SEQ) ------------
// grid: (BATCH*NHEAD, MSPLIT), 256 threads, 4x4 per-thread tile, atomic finish
#define MSPLIT 8
#define MCHUNK (SEQ / MSPLIT)   // 256

__global__ __launch_bounds__(256)
void ktv_kernel() {
    const int bh = blockIdx.x;
    const int b  = bh / NHEAD;
    const int h  = bh % NHEAD;
    const int mbase = blockIdx.y * MCHUNK;

    __shared__ float Ks[16][HDIM];
    __shared__ float Vs[16][HDIM];

    const int tid = threadIdx.x;
    const int t1 = (tid >> 4) * 4;   // d1 base (K dim of S)
    const int t2 = (tid & 15) * 4;   // d2 base (V dim of S)

    const float* Kb = g_K + ((size_t)b * SEQ) * HID + h * HDIM;
    const float* Vb = g_V + ((size_t)b * SEQ) * HID + h * HDIM;

    float acc[4][4];
#pragma unroll
    for (int i = 0; i < 4; ++i)
#pragma unroll
        for (int j = 0; j < 4; ++j) acc[i][j] = 0.0f;

    const int lrow = tid >> 4;            // 0..15
    const int lc4  = (tid & 15) * 4;      // 0..60

    for (int m0 = mbase; m0 < mbase + MCHUNK; m0 += 16) {
        float4 kv = *(const float4*)(Kb + (size_t)(m0 + lrow) * HID + lc4);
        float4 vv = *(const float4*)(Vb + (size_t)(m0 + lrow) * HID + lc4);
        *(float4*)&Ks[lrow][lc4] = kv;
        *(float4*)&Vs[lrow][lc4] = vv;
        __syncthreads();
#pragma unroll
        for (int m = 0; m < 16; ++m) {
            float a[4], v[4];
#pragma unroll
            for (int i = 0; i < 4; ++i) a[i] = Ks[m][t1 + i];
#pragma unroll
            for (int j = 0; j < 4; ++j) v[j] = Vs[m][t2 + j];
#pragma unroll
            for (int i = 0; i < 4; ++i)
#pragma unroll
                for (int j = 0; j < 4; ++j)
                    acc[i][j] = fmaf(a[i], v[j], acc[i][j]);
        }
        __syncthreads();
    }

    float* Sb = g_S + (size_t)bh * HDIM * HDIM;
#pragma unroll
    for (int i = 0; i < 4; ++i)
#pragma unroll
        for (int j = 0; j < 4; ++j)
            atomicAdd(&Sb[(t1 + i) * HDIM + t2 + j], acc[i][j]);
}

// ---------------- A[b,h] = Q_h @ S[b,h]  -> g_ATT interleaved ---------------
// grid: (BATCH*NHEAD, SEQ/128), 256 threads; each thread computes 4 rows x 8 cols
__global__ __launch_bounds__(256)
void qs_kernel() {
    const int bh = blockIdx.x;
    const int b  = bh / NHEAD;
    const int h  = bh % NHEAD;
    const int m0 = blockIdx.y * 128;

    __shared__ float Ss[HDIM][HDIM];   // 16 KB
    __shared__ float Qs[16][128];      // 8 KB (transposed k-major)

    const int tid = threadIdx.x;

    // load S tile fully: 4096 floats = 1024 float4; 4 per thread
    {
        const float* Sb = g_S + (size_t)bh * HDIM * HDIM;
#pragma unroll
        for (int it = 0; it < 4; ++it) {
            int idx = tid + it * 256;          // 0..1023 float4 index
            int row = idx >> 4;                // /16
            int c4  = (idx & 15) * 4;
            *(float4*)&Ss[row][c4] = *(const float4*)(Sb + row * HDIM + c4);
        }
    }

    const int ty = tid >> 3;     // 0..31 -> rows ty*4
    const int tx = tid & 7;      // 0..7  -> cols tx*8

    float acc[4][8];
#pragma unroll
    for (int i = 0; i < 4; ++i)
#pragma unroll
        for (int j = 0; j < 8; ++j) acc[i][j] = 0.0f;

    const float* Qb = g_Q + ((size_t)b * SEQ + m0) * HID + h * HDIM;

    for (int kb = 0; kb < 4; ++kb) {
        const int k0 = kb * 16;
        // load Q tile [128 rows][16 k] transposed: 512 float4, 2 per thread
#pragma unroll
        for (int it = 0; it < 2; ++it) {
            int idx = tid + it * 256;
            int row = idx >> 2;
            int kq  = (idx & 3) * 4;
            float4 v = *(const float4*)(Qb + (size_t)row * HID + k0 + kq);
            Qs[kq + 0][row] = v.x;
            Qs[kq + 1][row] = v.y;
            Qs[kq + 2][row] = v.z;
            Qs[kq + 3][row] = v.w;
        }
        __syncthreads();
#pragma unroll
        for (int kk = 0; kk < 16; ++kk) {
            float q[4], s[8];
#pragma unroll
            for (int i = 0; i < 4; ++i) q[i] = Qs[kk][ty * 4 + i];
            float4 s0 = *(const float4*)&Ss[k0 + kk][tx * 8];
            float4 s1 = *(const float4*)&Ss[k0 + kk][tx * 8 + 4];
            s[0]=s0.x; s[1]=s0.y; s[2]=s0.z; s[3]=s0.w;
            s[4]=s1.x; s[5]=s1.y; s[6]=s1.z; s[7]=s1.w;
#pragma unroll
            for (int i = 0; i < 4; ++i)
#pragma unroll
                for (int j = 0; j < 8; ++j)
                    acc[i][j] = fmaf(q[i], s[j], acc[i][j]);
        }
        __syncthreads();
    }

    // write to g_ATT[b, m, h*64 + col]
#pragma unroll
    for (int i = 0; i < 4; ++i) {
        float* dst = g_ATT + ((size_t)b * SEQ + m0 + ty * 4 + i) * HID + h * HDIM + tx * 8;
        *(float4*)(dst)     = make_float4(acc[i][0], acc[i][1], acc[i][2], acc[i][3]);
        *(float4*)(dst + 4) = make_float4(acc[i][4], acc[i][5], acc[i][6], acc[i][7]);
    }
}

// ---------------- launch ----------------------------------------------------
extern "C" void kernel_launch(void* const* d_in, const int* in_sizes, int n_in,
                              void* d_out, int out_size) {
    (void)in_sizes; (void)n_in; (void)out_size;
    const float* h   = (const float*)d_in[0];
    const float* Wq  = (const float*)d_in[1];
    const float* Wk  = (const float*)d_in[2];
    const float* Wv  = (const float*)d_in[3];
    // d_in[4] = Wspan (dead code in reference)
    const float* Wo  = (const float*)d_in[5];
    float* out = (float*)d_out;

    float *pQ, *pK, *pV, *pATT, *pS;
    cudaGetSymbolAddress((void**)&pQ,   g_Q);
    cudaGetSymbolAddress((void**)&pK,   g_K);
    cudaGetSymbolAddress((void**)&pV,   g_V);
    cudaGetSymbolAddress((void**)&pATT, g_ATT);
    cudaGetSymbolAddress((void**)&pS,   g_S);

    dim3 gGemm(HID / BN, ROWS / BM);   // (8, 32)
    sgemm_abT<<<gGemm, 256>>>(h, Wq, pQ, ROWS, HID, HID);
    sgemm_abT<<<gGemm, 256>>>(h, Wk, pK, ROWS, HID, HID);
    sgemm_abT<<<gGemm, 256>>>(h, Wv, pV, ROWS, HID, HID);

    int nS = BATCH * NHEAD * HDIM * HDIM;
    zero_kernel<<<(nS + 255) / 256, 256>>>(pS, nS);

    ktv_kernel<<<dim3(BATCH * NHEAD, MSPLIT), 256>>>();
    qs_kernel<<<dim3(BATCH * NHEAD, SEQ / 128), 256>>>();

    sgemm_abT<<<gGemm, 256>>>(pATT, Wo, out, ROWS, HID, HID);
}

// round 3
// speedup vs baseline: 2.0449x; 2.0449x over previous
#include <cuda_runtime.h>
#include <cuda_bf16.h>
#include <cstdint>

// Problem constants
#define BATCH 2
#define SEQ   2048
#define HID   1024
#define NHEAD 16
#define HDIM  64
#define ROWS  (BATCH * SEQ)      // 4096
#define KSP   2048               // split storage width: [hi | lo]
#define NQKV  3072               // fused QKV output width
#define NIT   96                 // 96 k-chunks of 32 (virtual K = 3072)

// ---------------- scratch (static device allocations; no cudaMalloc) --------
__device__ __nv_bfloat16 g_hs   [ROWS * KSP];   // h split [hi|lo]
__device__ __nv_bfloat16 g_Wqkvs[NQKV * KSP];   // [Wq;Wk;Wv] split
__device__ __nv_bfloat16 g_Wos  [HID  * KSP];
__device__ __nv_bfloat16 g_ATTs [ROWS * KSP];
__device__ float g_QKV[ROWS * NQKV];            // fused projections (fp32)
__device__ float g_ATT[ROWS * HID];
__device__ float g_S  [BATCH * NHEAD * HDIM * HDIM];

// ---------------- helpers ----------------------------------------------------
__device__ __forceinline__ uint32_t smem_u32(const void* p) {
    uint32_t a;
    asm("{ .reg .u64 t; cvta.to.shared.u64 t, %1; cvt.u32.u64 %0, t; }"
        : "=r"(a) : "l"(p));
    return a;
}
__device__ __forceinline__ void cp16(uint32_t dst, const void* src) {
    asm volatile("cp.async.cg.shared.global [%0], [%1], 16;"
                 :: "r"(dst), "l"(src));
}

// ---------------- split: X fp32 [rows,1024] -> Y bf16 [rows, 2048]=[hi|lo] ---
__global__ void split_kernel(const float* __restrict__ X,
                             __nv_bfloat16* __restrict__ Y, int rows) {
    int i = blockIdx.x * 256 + threadIdx.x;
    if (i >= rows * 256) return;
    int r = i >> 8;
    int c4 = (i & 255) * 4;
    float4 v = *(const float4*)(X + (size_t)r * HID + c4);
    float f[4] = {v.x, v.y, v.z, v.w};
    unsigned sh[4], sl[4];
#pragma unroll
    for (int j = 0; j < 4; ++j) {
        __nv_bfloat16 hb = __float2bfloat16(f[j]);
        float hf = __bfloat162float(hb);
        __nv_bfloat16 lb = __float2bfloat16(f[j] - hf);
        sh[j] = (unsigned)__bfloat16_as_ushort(hb);
        sl[j] = (unsigned)__bfloat16_as_ushort(lb);
    }
    uint2 ph = make_uint2(sh[0] | (sh[1] << 16), sh[2] | (sh[3] << 16));
    uint2 pl = make_uint2(sl[0] | (sl[1] << 16), sl[2] | (sl[3] << 16));
    unsigned short* yb = (unsigned short*)Y + (size_t)r * KSP;
    *(uint2*)(yb + c4)       = ph;
    *(uint2*)(yb + HID + c4) = pl;
}

// ---------------- bf16-split GEMM via mma.sync (m16n8k16) -------------------
// C[4096, N] fp32 = A2[4096,2048] x B2[N,2048]^T over virtual K=3072:
//   it chunk (32 wide): term = it/32; A uses lo iff term==2, B lo iff term==1.
// Tile 128x128, 8 warps (2m x 4n), warp tile 64x32, 3-stage cp.async.
// Smem rows padded to 80B (64B data) -> conflict-free ldmatrix, no swizzle.
#define LDB   80                 // smem row stride bytes
#define STAGE 20480              // (128*80)*2 tiles per stage
#define GSMEM (3 * STAGE)        // 61440

__global__ __launch_bounds__(256, 2)
void gemm_bf16(const __nv_bfloat16* __restrict__ A,
               const __nv_bfloat16* __restrict__ B,
               float* __restrict__ C, int N) {
    extern __shared__ char sm[];
    const int tid = threadIdx.x, lane = tid & 31, wid = tid >> 5;
    const int wm = wid & 1, wn = wid >> 1;
    const int bm = blockIdx.y * 128, bn = blockIdx.x * 128;
    const uint32_t sb = smem_u32(sm);
    const char* Ag = (const char*)A + (size_t)bm * (KSP * 2);
    const char* Bg = (const char*)B + (size_t)bn * (KSP * 2);

    float acc[4][4][4];
#pragma unroll
    for (int mt = 0; mt < 4; ++mt)
#pragma unroll
        for (int nt = 0; nt < 4; ++nt)
#pragma unroll
            for (int j = 0; j < 4; ++j) acc[mt][nt][j] = 0.0f;

    auto load_stage = [&](int it) {
        int s = it % 3;
        int term = it >> 5, kk = (it & 31) * 32;
        int ak = ((term == 2) ? 1024 : 0) + kk;
        int bk = ((term == 1) ? 1024 : 0) + kk;
        uint32_t da = sb + s * STAGE, db = da + 10240;
        const char* Ap = Ag + ak * 2;
        const char* Bp = Bg + bk * 2;
        int row = tid >> 2, c = (tid & 3) * 16;
        cp16(da + row * LDB + c,                Ap + (size_t)row * 4096 + c);
        cp16(da + (row + 64) * LDB + c,         Ap + (size_t)(row + 64) * 4096 + c);
        cp16(db + row * LDB + c,                Bp + (size_t)row * 4096 + c);
        cp16(db + (row + 64) * LDB + c,         Bp + (size_t)(row + 64) * 4096 + c);
        asm volatile("cp.async.commit_group;" ::: "memory");
    };

    load_stage(0);
    load_stage(1);

    for (int it = 0; it < NIT; ++it) {
        if (it < NIT - 1) asm volatile("cp.async.wait_group 1;" ::: "memory");
        else              asm volatile("cp.async.wait_group 0;" ::: "memory");
        __syncthreads();
        if (it + 2 < NIT) load_stage(it + 2);

        int s = it % 3;
        uint32_t abase = sb + s * STAGE +
                         (wm * 64 + (lane & 15)) * LDB + ((lane >> 4) & 1) * 16;
        uint32_t bbase = sb + s * STAGE + 10240 +
                         (wn * 32 + (lane & 7)) * LDB + ((lane >> 3) & 1) * 16;
#pragma unroll
        for (int ks = 0; ks < 2; ++ks) {
            uint32_t a[4][4], b[4][2];
#pragma unroll
            for (int mt = 0; mt < 4; ++mt)
                asm volatile(
                    "ldmatrix.sync.aligned.m8n8.x4.shared.b16 {%0,%1,%2,%3}, [%4];"
                    : "=r"(a[mt][0]), "=r"(a[mt][1]), "=r"(a[mt][2]), "=r"(a[mt][3])
                    : "r"(abase + ks * 32 + mt * (16 * LDB)));
#pragma unroll
            for (int nt = 0; nt < 4; ++nt)
                asm volatile(
                    "ldmatrix.sync.aligned.m8n8.x2.shared.b16 {%0,%1}, [%2];"
                    : "=r"(b[nt][0]), "=r"(b[nt][1])
                    : "r"(bbase + ks * 32 + nt * (8 * LDB)));
#pragma unroll
            for (int mt = 0; mt < 4; ++mt)
#pragma unroll
                for (int nt = 0; nt < 4; ++nt)
                    asm volatile(
                        "mma.sync.aligned.m16n8k16.row.col.f32.bf16.bf16.f32 "
                        "{%0,%1,%2,%3}, {%4,%5,%6,%7}, {%8,%9}, {%0,%1,%2,%3};"
                        : "+f"(acc[mt][nt][0]), "+f"(acc[mt][nt][1]),
                          "+f"(acc[mt][nt][2]), "+f"(acc[mt][nt][3])
                        : "r"(a[mt][0]), "r"(a[mt][1]), "r"(a[mt][2]), "r"(a[mt][3]),
                          "r"(b[nt][0]), "r"(b[nt][1]));
        }
    }

    // epilogue: direct float2 stores (C fragment layout)
#pragma unroll
    for (int mt = 0; mt < 4; ++mt)
#pragma unroll
        for (int nt = 0; nt < 4; ++nt) {
            int r0 = bm + wm * 64 + mt * 16 + (lane >> 2);
            int c0 = bn + wn * 32 + nt * 8 + (lane & 3) * 2;
            *(float2*)(C + (size_t)r0 * N + c0) =
                make_float2(acc[mt][nt][0], acc[mt][nt][1]);
            *(float2*)(C + (size_t)(r0 + 8) * N + c0) =
                make_float2(acc[mt][nt][2], acc[mt][nt][3]);
        }
}

// ---------------- zero S ----------------------------------------------------
__global__ void zero_kernel(float* __restrict__ p, int n) {
    int i = blockIdx.x * blockDim.x + threadIdx.x;
    if (i < n) p[i] = 0.0f;
}

// ---------------- S[b,h] = K_h^T @ V_h  (64x64, reduce over SEQ) ------------
#define MSPLIT 8
#define MCHUNK (SEQ / MSPLIT)   // 256

__global__ __launch_bounds__(256)
void ktv_kernel() {
    const int bh = blockIdx.x;
    const int b  = bh / NHEAD;
    const int h  = bh % NHEAD;
    const int mbase = blockIdx.y * MCHUNK;

    __shared__ float Ks[16][HDIM];
    __shared__ float Vs[16][HDIM];

    const int tid = threadIdx.x;
    const int t1 = (tid >> 4) * 4;
    const int t2 = (tid & 15) * 4;

    const float* Kb = g_QKV + ((size_t)b * SEQ) * NQKV + HID + h * HDIM;
    const float* Vb = g_QKV + ((size_t)b * SEQ) * NQKV + 2 * HID + h * HDIM;

    float acc[4][4];
#pragma unroll
    for (int i = 0; i < 4; ++i)
#pragma unroll
        for (int j = 0; j < 4; ++j) acc[i][j] = 0.0f;

    const int lrow = tid >> 4;
    const int lc4  = (tid & 15) * 4;

    for (int m0 = mbase; m0 < mbase + MCHUNK; m0 += 16) {
        float4 kv = *(const float4*)(Kb + (size_t)(m0 + lrow) * NQKV + lc4);
        float4 vv = *(const float4*)(Vb + (size_t)(m0 + lrow) * NQKV + lc4);
        *(float4*)&Ks[lrow][lc4] = kv;
        *(float4*)&Vs[lrow][lc4] = vv;
        __syncthreads();
#pragma unroll
        for (int m = 0; m < 16; ++m) {
            float a[4], v[4];
#pragma unroll
            for (int i = 0; i < 4; ++i) a[i] = Ks[m][t1 + i];
#pragma unroll
            for (int j = 0; j < 4; ++j) v[j] = Vs[m][t2 + j];
#pragma unroll
            for (int i = 0; i < 4; ++i)
#pragma unroll
                for (int j = 0; j < 4; ++j)
                    acc[i][j] = fmaf(a[i], v[j], acc[i][j]);
        }
        __syncthreads();
    }

    float* Sb = g_S + (size_t)bh * HDIM * HDIM;
#pragma unroll
    for (int i = 0; i < 4; ++i)
#pragma unroll
        for (int j = 0; j < 4; ++j)
            atomicAdd(&Sb[(t1 + i) * HDIM + t2 + j], acc[i][j]);
}

// ---------------- A[b,h] = Q_h @ S[b,h]  -> g_ATT interleaved ---------------
__global__ __launch_bounds__(256)
void qs_kernel() {
    const int bh = blockIdx.x;
    const int b  = bh / NHEAD;
    const int h  = bh % NHEAD;
    const int m0 = blockIdx.y * 128;

    __shared__ float Ss[HDIM][HDIM];
    __shared__ float Qs[16][128];

    const int tid = threadIdx.x;

    {
        const float* Sb = g_S + (size_t)bh * HDIM * HDIM;
#pragma unroll
        for (int it = 0; it < 4; ++it) {
            int idx = tid + it * 256;
            int row = idx >> 4;
            int c4  = (idx & 15) * 4;
            *(float4*)&Ss[row][c4] = *(const float4*)(Sb + row * HDIM + c4);
        }
    }

    const int ty = tid >> 3;
    const int tx = tid & 7;

    float acc[4][8];
#pragma unroll
    for (int i = 0; i < 4; ++i)
#pragma unroll
        for (int j = 0; j < 8; ++j) acc[i][j] = 0.0f;

    const float* Qb = g_QKV + ((size_t)b * SEQ + m0) * NQKV + h * HDIM;

    for (int kb = 0; kb < 4; ++kb) {
        const int k0 = kb * 16;
#pragma unroll
        for (int it = 0; it < 2; ++it) {
            int idx = tid + it * 256;
            int row = idx >> 2;
            int kq  = (idx & 3) * 4;
            float4 v = *(const float4*)(Qb + (size_t)row * NQKV + k0 + kq);
            Qs[kq + 0][row] = v.x;
            Qs[kq + 1][row] = v.y;
            Qs[kq + 2][row] = v.z;
            Qs[kq + 3][row] = v.w;
        }
        __syncthreads();
#pragma unroll
        for (int kk = 0; kk < 16; ++kk) {
            float q[4], s[8];
#pragma unroll
            for (int i = 0; i < 4; ++i) q[i] = Qs[kk][ty * 4 + i];
            float4 s0 = *(const float4*)&Ss[k0 + kk][tx * 8];
            float4 s1 = *(const float4*)&Ss[k0 + kk][tx * 8 + 4];
            s[0]=s0.x; s[1]=s0.y; s[2]=s0.z; s[3]=s0.w;
            s[4]=s1.x; s[5]=s1.y; s[6]=s1.z; s[7]=s1.w;
#pragma unroll
            for (int i = 0; i < 4; ++i)
#pragma unroll
                for (int j = 0; j < 8; ++j)
                    acc[i][j] = fmaf(q[i], s[j], acc[i][j]);
        }
        __syncthreads();
    }

#pragma unroll
    for (int i = 0; i < 4; ++i) {
        float* dst = g_ATT + ((size_t)b * SEQ + m0 + ty * 4 + i) * HID + h * HDIM + tx * 8;
        *(float4*)(dst)     = make_float4(acc[i][0], acc[i][1], acc[i][2], acc[i][3]);
        *(float4*)(dst + 4) = make_float4(acc[i][4], acc[i][5], acc[i][6], acc[i][7]);
    }
}

// ---------------- launch ----------------------------------------------------
extern "C" void kernel_launch(void* const* d_in, const int* in_sizes, int n_in,
                              void* d_out, int out_size) {
    (void)in_sizes; (void)n_in; (void)out_size;
    const float* h   = (const float*)d_in[0];
    const float* Wq  = (const float*)d_in[1];
    const float* Wk  = (const float*)d_in[2];
    const float* Wv  = (const float*)d_in[3];
    // d_in[4] = Wspan (dead code in reference)
    const float* Wo  = (const float*)d_in[5];
    float* out = (float*)d_out;

    __nv_bfloat16 *pHs, *pWqkvs, *pWos, *pATTs;
    float *pQKV, *pATT, *pS;
    cudaGetSymbolAddress((void**)&pHs,    g_hs);
    cudaGetSymbolAddress((void**)&pWqkvs, g_Wqkvs);
    cudaGetSymbolAddress((void**)&pWos,   g_Wos);
    cudaGetSymbolAddress((void**)&pATTs,  g_ATTs);
    cudaGetSymbolAddress((void**)&pQKV,   g_QKV);
    cudaGetSymbolAddress((void**)&pATT,   g_ATT);
    cudaGetSymbolAddress((void**)&pS,     g_S);

    cudaFuncSetAttribute(gemm_bf16,
                         cudaFuncAttributeMaxDynamicSharedMemorySize, GSMEM);

    // 1) split inputs to bf16 [hi|lo]
    split_kernel<<<ROWS, 256>>>(h,  pHs, ROWS);
    split_kernel<<<HID,  256>>>(Wq, pWqkvs,                          HID);
    split_kernel<<<HID,  256>>>(Wk, pWqkvs + (size_t)HID * KSP,      HID);
    split_kernel<<<HID,  256>>>(Wv, pWqkvs + (size_t)2 * HID * KSP,  HID);
    split_kernel<<<HID,  256>>>(Wo, pWos, HID);

    // 2) fused QKV projection on tensor cores
    gemm_bf16<<<dim3(NQKV / 128, ROWS / 128), 256, GSMEM>>>(pHs, pWqkvs, pQKV, NQKV);

    // 3) attention via associativity: ATT = Q (K^T V)
    int nS = BATCH * NHEAD * HDIM * HDIM;
    zero_kernel<<<(nS + 255) / 256, 256>>>(pS, nS);
    ktv_kernel<<<dim3(BATCH * NHEAD, MSPLIT), 256>>>();
    qs_kernel<<<dim3(BATCH * NHEAD, SEQ / 128), 256>>>();

    // 4) output projection
    split_kernel<<<ROWS, 256>>>(pATT, pATTs, ROWS);
    gemm_bf16<<<dim3(HID / 128, ROWS / 128), 256, GSMEM>>>(pATTs, pWos, out, HID);
}